// round 10
// baseline (speedup 1.0000x reference)
#include <cuda_runtime.h>

// RNNBlock: out = relu( RNN_backwards(x; w_in, w_rec, b_rnn) @ w_d + b_d )
// fp32 exact, packed f32x2 FMA. R10 = R7 (7131us champion) with ONE change:
// w-chunk staging via cp.async.bulk (single elected thread, mbarrier
// complete_tx) instead of 2048 per-thread cp.async ops -> frees ~4096
// cyc/chunk/SMSP of LSU issue that was co-saturating against the LDS stream.

typedef unsigned long long u64;

#define B_TOT    32768
#define T_STEPS  79
#define F_IN     16
#define C_DIM    256
#define NSM      148      // persistent grid size
#define NTHREADS 512      // 16 warps
#define BW       7        // batch rows per warp
#define PASS_ROWS (16 * BW)   // 112 rows per pass
#define CHUNK    32       // w rows per smem chunk (32 KB)
#define CPBYTES  (CHUNK * C_DIM * 4)

// smem: h[112*256] | wbuf0[32*256] | wbuf1[32*256] | w_in[16*256] | xs[16*128] | mbar[2]
#define SM_H     0
#define SM_W0    (PASS_ROWS * C_DIM)
#define SM_W1    (SM_W0 + CHUNK * C_DIM)
#define SM_WI    (SM_W1 + CHUNK * C_DIM)
#define SM_XS    (SM_WI + F_IN * C_DIM)
#define SM_MBAR  (SM_XS + 16 * 8 * F_IN)   // 2 x u64, 8B-aligned (float idx even)
#define SMEM_FLOATS (SM_MBAR + 4)
#define SMEM_BYTES  (SMEM_FLOATS * 4)      // 204816 B

__device__ __forceinline__ u64 pack2(float lo, float hi) {
    u64 r; asm("mov.b64 %0, {%1, %2};" : "=l"(r) : "f"(lo), "f"(hi)); return r;
}
__device__ __forceinline__ u64 dup2(float v) {
    u64 r; asm("mov.b64 %0, {%1, %1};" : "=l"(r) : "f"(v)); return r;
}
__device__ __forceinline__ void unpack2(u64 v, float& lo, float& hi) {
    asm("mov.b64 {%0, %1}, %2;" : "=f"(lo), "=f"(hi) : "l"(v));
}
__device__ __forceinline__ void fma2(u64& d, u64 a, u64 b) {
    asm("fma.rn.f32x2 %0, %1, %2, %0;" : "+l"(d) : "l"(a), "l"(b));
}

__device__ __forceinline__ unsigned smem_u32(const void* p) {
    return (unsigned)__cvta_generic_to_shared(p);
}
__device__ __forceinline__ void mbar_init(unsigned mbar, unsigned count) {
    asm volatile("mbarrier.init.shared::cta.b64 [%0], %1;"
                 :: "r"(mbar), "r"(count) : "memory");
}
__device__ __forceinline__ void mbar_expect(unsigned mbar, unsigned bytes) {
    asm volatile("mbarrier.arrive.expect_tx.shared::cta.b64 _, [%0], %1;"
                 :: "r"(mbar), "r"(bytes) : "memory");
}
__device__ __forceinline__ void bulk_ld(unsigned dst, const float* src, unsigned mbar) {
    asm volatile(
        "cp.async.bulk.shared::cta.global.mbarrier::complete_tx::bytes [%0], [%1], %2, [%3];"
        :: "r"(dst), "l"(src), "r"((unsigned)CPBYTES), "r"(mbar) : "memory");
}
__device__ __forceinline__ void mbar_wait(unsigned mbar, unsigned parity) {
    asm volatile(
        "{\n\t"
        ".reg .pred P;\n\t"
        "WAIT_%=:\n\t"
        "mbarrier.try_wait.parity.acquire.cta.shared::cta.b64 P, [%0], %1, 10000000;\n\t"
        "@!P bra WAIT_%=;\n\t"
        "}"
        :: "r"(mbar), "r"(parity) : "memory");
}

// acc[b][p] += h[bloc+b][k] * W[k][2*lane + 64*p (+1)]  for k in 0..255.
// W streamed in 32-row chunks via cp.async.bulk, double-buffered; one
// mbarrier per buffer, parity tracked by u0/u1 (uniform across threads).
// Inner compute loop byte-identical to R7.
__device__ __forceinline__ void mm256(
    const float* __restrict__ wglob,
    const float* __restrict__ wbuf0, const float* __restrict__ wbuf1,
    unsigned wb0a, unsigned wb1a, unsigned mb0, unsigned mb1,
    unsigned& u0, unsigned& u1,
    const float* __restrict__ hbase,      // h_sm + bloc*C_DIM
    int c2, int tid, u64 acc[BW][4])
{
    if (tid == 0) {
        mbar_expect(mb0, CPBYTES); bulk_ld(wb0a, wglob, mb0);
        mbar_expect(mb1, CPBYTES); bulk_ld(wb1a, wglob + CHUNK * C_DIM, mb1);
    }
    #pragma unroll 1
    for (int kc = 0; kc < 8; ++kc) {
        const bool odd = (kc & 1);
        mbar_wait(odd ? mb1 : mb0, (odd ? u1 : u0) & 1);   // acquire: data visible
        if (odd) ++u1; else ++u0;

        const float* wc = odd ? wbuf1 : wbuf0;
        const float* hk = hbase + kc * CHUNK;
        #pragma unroll 2
        for (int kk = 0; kk < CHUNK; ++kk) {
            const float* wr = wc + kk * C_DIM + c2;    // lane-contiguous
            u64 wp0 = *(const u64*)(wr);
            u64 wp1 = *(const u64*)(wr + 64);
            u64 wp2 = *(const u64*)(wr + 128);
            u64 wp3 = *(const u64*)(wr + 192);
            #pragma unroll
            for (int b = 0; b < BW; ++b) {
                u64 hd = dup2(hk[b * C_DIM + kk]);     // warp-broadcast LDS
                fma2(acc[b][0], hd, wp0);
                fma2(acc[b][1], hd, wp1);
                fma2(acc[b][2], hd, wp2);
                fma2(acc[b][3], hd, wp3);
            }
        }
        __syncthreads();                               // buffer kc consumed
        if (kc + 2 < 8 && tid == 0) {
            unsigned mb = odd ? mb1 : mb0;
            mbar_expect(mb, CPBYTES);
            bulk_ld(odd ? wb1a : wb0a, wglob + (kc + 2) * CHUNK * C_DIM, mb);
        }
    }
}

__global__ void __launch_bounds__(NTHREADS, 1)
rnn_fused(const float* __restrict__ x,     const float* __restrict__ w_in,
          const float* __restrict__ w_rec, const float* __restrict__ b_rnn,
          const float* __restrict__ w_d,   const float* __restrict__ b_d,
          float* __restrict__ out)
{
    extern __shared__ float smem[];
    float* h_sm  = smem + SM_H;
    float* wbuf0 = smem + SM_W0;
    float* wbuf1 = smem + SM_W1;
    float* wi_sm = smem + SM_WI;

    const int tid  = threadIdx.x;
    const int lane = tid & 31;
    const int wid  = tid >> 5;
    const int c2   = lane << 1;             // base column; pairs at +0,+64,+128,+192
    const int bloc = wid * BW;              // 7 batch rows per warp
    float* xs_w = smem + SM_XS + wid * (8 * F_IN);   // warp-private x stage

    const unsigned wb0a = smem_u32(wbuf0);
    const unsigned wb1a = smem_u32(wbuf1);
    const unsigned mb0  = smem_u32(smem + SM_MBAR);
    const unsigned mb1  = mb0 + 8;
    unsigned u0 = 0, u1 = 0;                // per-buffer phase counters (uniform)

    if (tid == 0) { mbar_init(mb0, 1); mbar_init(mb1, 1); }

    // balanced contiguous batch range for this CTA (221 or 222 rows)
    const long row_start = ((long)blockIdx.x * B_TOT) / NSM;
    const long row_end   = ((long)(blockIdx.x + 1) * B_TOT) / NSM;

    // stage w_in once (plain row-major)
    {
        const float4* src = (const float4*)w_in;
        float4* dst = (float4*)wi_sm;
        for (int i = tid; i < (F_IN * C_DIM) / 4; i += NTHREADS) dst[i] = src[i];
    }
    u64 brnn[4], bd[4];
    #pragma unroll
    for (int p = 0; p < 4; ++p) {
        brnn[p] = pack2(b_rnn[c2 + 64*p], b_rnn[c2 + 64*p + 1]);
        bd[p]   = pack2(b_d[c2 + 64*p],   b_d[c2 + 64*p + 1]);
    }
    __syncthreads();                        // covers mbar_init + wi_sm visibility

    u64 acc[BW][4];
    const float* hbase = h_sm + bloc * C_DIM;
    const int r = lane >> 2, q = lane & 3;  // x staging: lane holds quad q of row r

    #pragma unroll 1
    for (int pass = 0; pass < 2; ++pass) {
        const long rbase = row_start + pass * PASS_ROWS + bloc;  // warp's first row

        #pragma unroll 1
        for (int s = 0; s < T_STEPS; ++s) {
            const int t = T_STEPS - 1 - s;      // go_backwards

            // ---- stage x[:,t,:] for this warp's 7 rows (warp-private smem) ----
            __syncwarp();                       // prev step's reads done
            if (lane < BW * 4) {                // 7 rows x 4 quads = 28 lanes
                long grow = rbase + r;
                if (grow > B_TOT - 1) grow = B_TOT - 1;   // clamp (masked later)
                const float4 xq = *(const float4*)(x + (grow * T_STEPS + t) * F_IN + q * 4);
                *(float4*)(xs_w + r * F_IN + q * 4) = xq;
            }
            __syncwarp();

            // ---- acc = b_rnn + x_t @ w_in ----
            #pragma unroll
            for (int b = 0; b < BW; ++b)
                #pragma unroll
                for (int p = 0; p < 4; ++p) acc[b][p] = brnn[p];

            #pragma unroll 4
            for (int f = 0; f < F_IN; ++f) {
                const float* wr = wi_sm + f * C_DIM + c2;
                u64 wp0 = *(const u64*)(wr);
                u64 wp1 = *(const u64*)(wr + 64);
                u64 wp2 = *(const u64*)(wr + 128);
                u64 wp3 = *(const u64*)(wr + 192);
                #pragma unroll
                for (int b = 0; b < BW; ++b) {
                    u64 xd = dup2(xs_w[b * F_IN + f]);
                    fma2(acc[b][0], xd, wp0);
                    fma2(acc[b][1], xd, wp1);
                    fma2(acc[b][2], xd, wp2);
                    fma2(acc[b][3], xd, wp3);
                }
            }

            // ---- recurrent term: acc += h @ w_rec (skip at s=0: h==0) ----
            if (s > 0) mm256(w_rec, wbuf0, wbuf1, wb0a, wb1a, mb0, mb1,
                             u0, u1, hbase, c2, tid, acc);

            // ---- relu + writeback h (warp-private rows, lane-contiguous) ----
            #pragma unroll
            for (int b = 0; b < BW; ++b) {
                float* hrow = h_sm + (bloc + b) * C_DIM + c2;
                #pragma unroll
                for (int p = 0; p < 4; ++p) {
                    float lo, hi; unpack2(acc[b][p], lo, hi);
                    lo = fmaxf(lo, 0.f); hi = fmaxf(hi, 0.f);
                    *(u64*)(hrow + 64*p) = pack2(lo, hi);
                }
            }
        }

        // ---- dense head: out = relu(h_last @ w_d + b_d), masked store ----
        #pragma unroll
        for (int b = 0; b < BW; ++b)
            #pragma unroll
            for (int p = 0; p < 4; ++p) acc[b][p] = bd[p];

        mm256(w_d, wbuf0, wbuf1, wb0a, wb1a, mb0, mb1,
              u0, u1, hbase, c2, tid, acc);

        #pragma unroll
        for (int b = 0; b < BW; ++b) {
            const long grow = rbase + b;
            if (grow < row_end) {
                float* orow = out + grow * C_DIM + c2;
                #pragma unroll
                for (int p = 0; p < 4; ++p) {
                    float lo, hi; unpack2(acc[b][p], lo, hi);
                    float2 v = make_float2(fmaxf(lo, 0.f), fmaxf(hi, 0.f));
                    *(float2*)(orow + 64*p) = v;
                }
            }
        }
        // mm256 ended with __syncthreads(): wbufs free; h rewritten next pass
        // only by the owning warp, so no extra barrier needed.
    }
}

extern "C" void kernel_launch(void* const* d_in, const int* in_sizes, int n_in,
                              void* d_out, int out_size)
{
    const float* x     = (const float*)d_in[0];
    const float* w_in  = (const float*)d_in[1];
    const float* w_rec = (const float*)d_in[2];
    const float* b_rnn = (const float*)d_in[3];
    const float* w_d   = (const float*)d_in[4];
    const float* b_d   = (const float*)d_in[5];
    float* out = (float*)d_out;

    cudaFuncSetAttribute(rnn_fused, cudaFuncAttributeMaxDynamicSharedMemorySize, SMEM_BYTES);

    rnn_fused<<<NSM, NTHREADS, SMEM_BYTES>>>(x, w_in, w_rec, b_rnn, w_d, b_d, out);
}